// round 1
// baseline (speedup 1.0000x reference)
#include <cuda_runtime.h>
#include <math.h>

#define BATCH 2
#define CH    128
#define HH    64
#define WW    64
#define QPB   9216
#define NQ    18432
#define NHEAD 4
#define KWIN  7
#define KAREA 49

// ---------------- scratch (static device memory; no allocation) ----------------
__device__ float g_ft[BATCH*HH*WW*CH];   // feat NHWC (for skip)
__device__ float g_fq[BATCH*HH*WW*CH];   // conv q NHWC
__device__ float g_fk[BATCH*HH*WW*CH];   // conv k NHWC
__device__ float g_fv[BATCH*HH*WW*CH];   // conv v NHWC
__device__ float g_wt[3*9*CH*CH];        // conv weights [conv][kk][ci][co]
__device__ float g_w0t[128*256];         // w0 transposed [k][j] (first 128 inputs)
__device__ float g_w1t[256*128];         // w1 transposed [k][o]
__device__ float g_c0[2*256];            // per-batch effective bias for hidden
__device__ float g_agg[NQ*CH];           // attention output

// ---------------- prep kernels ----------------
__global__ void prep_w_kernel(const float* __restrict__ qw,
                              const float* __restrict__ kw,
                              const float* __restrict__ vw) {
    int idx = blockIdx.x * blockDim.x + threadIdx.x;
    const int per = 9 * CH * CH;
    if (idx >= 3 * per) return;
    int c = idx / per; int r = idx - c * per;
    int kk = r / (CH * CH);
    int ci = (r / CH) % CH;
    int co = r % CH;
    const float* w = (c == 0) ? qw : ((c == 1) ? kw : vw);
    g_wt[idx] = w[(co * CH + ci) * 9 + kk];
}

__global__ void prep_x_kernel(const float* __restrict__ x) {
    int idx = blockIdx.x * blockDim.x + threadIdx.x;
    if (idx >= BATCH * HH * WW * CH) return;
    int c = idx % CH;
    int p = (idx / CH) % (HH * WW);
    int b = idx / (CH * HH * WW);
    g_ft[idx] = x[(b * CH + c) * (HH * WW) + p];
}

__global__ void prep_small_kernel(const float* __restrict__ w0,
                                  const float* __restrict__ b0,
                                  const float* __restrict__ w1,
                                  const float* __restrict__ cell) {
    int idx = blockIdx.x * blockDim.x + threadIdx.x;
    if (idx < 32768) {
        int k = idx / 256, j = idx % 256;
        g_w0t[idx] = w0[j * 130 + k];
    } else if (idx < 65536) {
        int r = idx - 32768;
        int k = r / 128, o = r % 128;
        g_w1t[r] = w1[o * 256 + k];
    } else if (idx < 66048) {
        int r = idx - 65536;
        int b = r / 256, j = r % 256;
        float rc0 = cell[b * 2 + 0] * 64.0f;
        float rc1 = cell[b * 2 + 1] * 64.0f;
        g_c0[r] = b0[j] + w0[j * 130 + 128] * rc0 + w0[j * 130 + 129] * rc1;
    }
}

// ---------------- conv3x3 (NCHW in -> NHWC out) ----------------
// grid: (64 tiles of 8x8, batch=2, conv=3); block 256.
// thread t: pixel group pxg=t&15 -> 4 pixels {p, p+16, p+32, p+48}; cog=t>>4 -> 8 output channels.
__global__ __launch_bounds__(256) void conv_kernel(const float* __restrict__ x,
                                                   const float* __restrict__ qb,
                                                   const float* __restrict__ kb,
                                                   const float* __restrict__ vb) {
    __shared__ float sp[100 * 33];   // input patch [pix 10x10][ci 32, pad 33]
    __shared__ float sw[32 * 128];   // weights [ci][co]

    int t = threadIdx.x;
    int z = blockIdx.z;
    int b = blockIdx.y;
    int ty = (blockIdx.x >> 3) << 3;
    int tx = (blockIdx.x & 7) << 3;

    const float* wt = g_wt + z * 9 * CH * CH;
    const float* bias = (z == 0) ? qb : ((z == 1) ? kb : vb);
    float* outp = (z == 0) ? g_fq : ((z == 1) ? g_fk : g_fv);

    int pxg = t & 15;
    int cog = t >> 4;

    int ppix[4];
#pragma unroll
    for (int m = 0; m < 4; m++) {
        int p = pxg + 16 * m;
        ppix[m] = (p >> 3) * 10 + (p & 7);
    }

    float acc[4][8];
#pragma unroll
    for (int m = 0; m < 4; m++)
#pragma unroll
        for (int n = 0; n < 8; n++) acc[m][n] = 0.0f;

    for (int cc = 0; cc < 4; cc++) {
        __syncthreads();
        // load 10x10x32 input patch (zero pad at borders)
        for (int e = t; e < 3300; e += 256) {
            int ci = e / 100; int pix = e - ci * 100;
            int yy = pix / 10; int xx = pix - yy * 10;
            int gy = ty - 1 + yy;
            int gx = tx - 1 + xx;
            float v = 0.0f;
            if ((unsigned)gy < 64u && (unsigned)gx < 64u)
                v = x[((b * CH + cc * 32 + ci) * HH + gy) * WW + gx];
            sp[pix * 33 + ci] = v;
        }
        for (int kk = 0; kk < 9; kk++) {
            __syncthreads();
            {
                const float4* src = (const float4*)(wt + kk * CH * CH + cc * 32 * CH);
                float4* dst = (float4*)sw;
                for (int i = t; i < 1024; i += 256) dst[i] = src[i];
            }
            __syncthreads();
            int koff = (kk / 3) * 10 + (kk % 3);
#pragma unroll 8
            for (int ci = 0; ci < 32; ci++) {
                float4 wa = *(const float4*)&sw[ci * 128 + cog * 8];
                float4 wb = *(const float4*)&sw[ci * 128 + cog * 8 + 4];
#pragma unroll
                for (int m = 0; m < 4; m++) {
                    float pv = sp[(ppix[m] + koff) * 33 + ci];
                    acc[m][0] += pv * wa.x; acc[m][1] += pv * wa.y;
                    acc[m][2] += pv * wa.z; acc[m][3] += pv * wa.w;
                    acc[m][4] += pv * wb.x; acc[m][5] += pv * wb.y;
                    acc[m][6] += pv * wb.z; acc[m][7] += pv * wb.w;
                }
            }
        }
    }

    float bs[8];
#pragma unroll
    for (int n = 0; n < 8; n++) bs[n] = bias[cog * 8 + n];

#pragma unroll
    for (int m = 0; m < 4; m++) {
        int p = pxg + 16 * m;
        int gy = ty + (p >> 3);
        int gx = tx + (p & 7);
        float* o = outp + ((b * HH + gy) * WW + gx) * CH + cog * 8;
        *(float4*)(o) = make_float4(acc[m][0] + bs[0], acc[m][1] + bs[1],
                                    acc[m][2] + bs[2], acc[m][3] + bs[3]);
        *(float4*)(o + 4) = make_float4(acc[m][4] + bs[4], acc[m][5] + bs[5],
                                        acc[m][6] + bs[6], acc[m][7] + bs[7]);
    }
}

// ---------------- attention: one warp per query ----------------
__global__ __launch_bounds__(256) void attn_kernel(const float* __restrict__ coord,
                                                   const float* __restrict__ pbw,
                                                   const float* __restrict__ pbb) {
    __shared__ float slog[8][NHEAD][KAREA];
    __shared__ float sbias[8][2][KWIN][NHEAD];
    __shared__ float spbw[NHEAD * 64];
    __shared__ float spbb[NHEAD];

    int t = threadIdx.x;
    int w = t >> 5;
    int lane = t & 31;
    if (t < NHEAD * 64) spbw[t] = pbw[t];
    if (t < NHEAD) spbb[t] = pbb[t];
    __syncthreads();

    int q = blockIdx.x * 8 + w;
    int b = q / QPB;
    float cy = coord[q * 2 + 0];
    float cx = coord[q * 2 + 1];
    float py = ((cy + 1.0f) * 64.0f - 1.0f) * 0.5f;
    float px = ((cx + 1.0f) * 64.0f - 1.0f) * 0.5f;
    float riy = rintf(py), rix = rintf(px);
    int iy0 = (int)riy, ix0 = (int)rix;
    float fy = py - riy, fx = px - rix;
    int h = lane >> 3;

    // bilinear q sample (zeros padding), 4 channels per lane (c = 4*lane..)
    float qv0 = 0.f, qv1 = 0.f, qv2 = 0.f, qv3 = 0.f;
    {
        float yf = floorf(py), xf = floorf(px);
        int y0 = (int)yf, x0 = (int)xf;
        float wy1 = py - yf, wx1 = px - xf;
#pragma unroll
        for (int dy2 = 0; dy2 < 2; dy2++)
#pragma unroll
            for (int dx2 = 0; dx2 < 2; dx2++) {
                int iy = y0 + dy2, ix = x0 + dx2;
                if ((unsigned)iy < 64u && (unsigned)ix < 64u) {
                    float wg = (dy2 ? wy1 : 1.0f - wy1) * (dx2 ? wx1 : 1.0f - wx1);
                    const float4 v = *(const float4*)(g_fq + (((b * HH + iy) * WW + ix) * CH + 4 * lane));
                    qv0 += wg * v.x; qv1 += wg * v.y; qv2 += wg * v.z; qv3 += wg * v.w;
                }
            }
    }

    // separable positional-bias tables: lanes 0..13 compute g_h(rel_y[d]) / e_h(rel_x[d])
    if (lane < 14) {
        int a = lane / 7;
        int dpos = lane - a * 7;
        float rel = 2.0f * ((a ? fx : fy) - (float)(dpos - 3));
        float a0 = 0.f, a1 = 0.f, a2 = 0.f, a3 = 0.f;
        const float step = 10.0f / 15.0f;
#pragma unroll
        for (int i = 0; i < 16; i++) {
            float fr = (i == 15) ? 1023.0f : (exp2f((float)i * step) - 1.0f);
            float s, c;
            sincosf(rel * fr, &s, &c);
            int si = a * 16 + i, ci2 = 32 + a * 16 + i;
            a0 += spbw[0 * 64 + si] * s + spbw[0 * 64 + ci2] * c;
            a1 += spbw[1 * 64 + si] * s + spbw[1 * 64 + ci2] * c;
            a2 += spbw[2 * 64 + si] * s + spbw[2 * 64 + ci2] * c;
            a3 += spbw[3 * 64 + si] * s + spbw[3 * 64 + ci2] * c;
        }
        if (a == 0) { a0 += spbb[0]; a1 += spbb[1]; a2 += spbb[2]; a3 += spbb[3]; }
        sbias[w][a][dpos][0] = a0; sbias[w][a][dpos][1] = a1;
        sbias[w][a][dpos][2] = a2; sbias[w][a][dpos][3] = a3;
    }
    __syncwarp();

    // pass 1: logits
    const float scale = 0.17677669529663687f;
    {
        int k = 0;
        for (int dy = -3; dy <= 3; dy++) {
            for (int dx = -3; dx <= 3; dx++, k++) {
                int iy = iy0 + dy, ix = ix0 + dx;
                float dot = 0.0f;
                if ((unsigned)iy < 64u && (unsigned)ix < 64u) {
                    const float4 kv = *(const float4*)(g_fk + (((b * HH + iy) * WW + ix) * CH + 4 * lane));
                    dot = qv0 * kv.x + qv1 * kv.y + qv2 * kv.z + qv3 * kv.w;
                }
                dot += __shfl_xor_sync(0xffffffffu, dot, 1);
                dot += __shfl_xor_sync(0xffffffffu, dot, 2);
                dot += __shfl_xor_sync(0xffffffffu, dot, 4);
                float lg = dot * scale + sbias[w][0][dy + 3][h] + sbias[w][1][dx + 3][h];
                if ((lane & 7) == 0) slog[w][h][k] = lg;
            }
        }
    }
    __syncwarp();

    float mx = -1e30f;
    for (int kk = 0; kk < KAREA; kk++) mx = fmaxf(mx, slog[w][h][kk]);
    float ssum = 0.0f;
    for (int kk = 0; kk < KAREA; kk++) ssum += expf(slog[w][h][kk] - mx);
    float inv = 1.0f / ssum;

    // pass 2: aggregate v
    float a0 = 0.f, a1 = 0.f, a2 = 0.f, a3 = 0.f;
    {
        int k = 0;
        for (int dy = -3; dy <= 3; dy++) {
            for (int dx = -3; dx <= 3; dx++, k++) {
                int iy = iy0 + dy, ix = ix0 + dx;
                if ((unsigned)iy < 64u && (unsigned)ix < 64u) {
                    float wg = expf(slog[w][h][k] - mx) * inv;
                    const float4 v = *(const float4*)(g_fv + (((b * HH + iy) * WW + ix) * CH + 4 * lane));
                    a0 += wg * v.x; a1 += wg * v.y; a2 += wg * v.z; a3 += wg * v.w;
                }
            }
        }
    }
    *(float4*)(g_agg + q * CH + 4 * lane) = make_float4(a0, a1, a2, a3);
}

// ---------------- MLP + skip ----------------
// block: 64 queries, 256 threads (16 q-groups x 16 j/o-groups). dynamic smem:
//   GEMM1: sX [64][130] @ 0 (8320 floats), sW [32][256] @ 8320 (8192)
//   GEMM2: sH [64][258] @ 0 (16512 floats), sW1 [64][128] @ 16512 (8192)
#define MLP_SMEM_FLOATS 24704
__global__ __launch_bounds__(256) void mlp_kernel(const float* __restrict__ coord,
                                                  const float* __restrict__ b1,
                                                  float* __restrict__ out) {
    extern __shared__ float sm[];
    float* sX = sm;
    float* sW = sm + 64 * 130;

    int t = threadIdx.x;
    int qbase = blockIdx.x * 64;
    int b = qbase / QPB;
    int qg = t & 15;
    int jg = t >> 4;

    for (int i = t; i < 64 * 128; i += 256) {
        int r = i >> 7, c2 = i & 127;
        sX[r * 130 + c2] = g_agg[(qbase + r) * CH + c2];
    }

    float acc1[4][16];
#pragma unroll
    for (int m = 0; m < 4; m++)
#pragma unroll
        for (int n = 0; n < 16; n++) acc1[m][n] = 0.0f;

    for (int kc = 0; kc < 4; kc++) {
        __syncthreads();
        {
            const float* src = g_w0t + kc * 32 * 256;
            for (int i = t; i < 8192; i += 256) sW[i] = src[i];
        }
        __syncthreads();
        for (int k = 0; k < 32; k++) {
            float xv[4];
#pragma unroll
            for (int m = 0; m < 4; m++) xv[m] = sX[(qg + 16 * m) * 130 + kc * 32 + k];
            const float* wr = &sW[k * 256 + jg * 16];
            float wrg[16];
#pragma unroll
            for (int n = 0; n < 16; n += 4) {
                float4 v = *(const float4*)(wr + n);
                wrg[n] = v.x; wrg[n + 1] = v.y; wrg[n + 2] = v.z; wrg[n + 3] = v.w;
            }
#pragma unroll
            for (int m = 0; m < 4; m++)
#pragma unroll
                for (int n = 0; n < 16; n++) acc1[m][n] += xv[m] * wrg[n];
        }
    }
    __syncthreads();

    // gelu + redistribute H through smem
    float* sH = sm;
    float* sW1 = sm + 64 * 258;
#pragma unroll
    for (int m = 0; m < 4; m++) {
        int qq = qg + 16 * m;
#pragma unroll
        for (int jj = 0; jj < 16; jj++) {
            int j = jg * 16 + jj;
            float v = acc1[m][jj] + g_c0[b * 256 + j];
            float hgl = 0.5f * v * (1.0f + erff(v * 0.70710678118654752f));
            sH[qq * 258 + j] = hgl;
        }
    }

    int og = jg;
    float acc2[4][8];
#pragma unroll
    for (int m = 0; m < 4; m++)
#pragma unroll
        for (int n = 0; n < 8; n++) acc2[m][n] = 0.0f;

    for (int kc = 0; kc < 4; kc++) {
        __syncthreads();
        {
            const float* src = g_w1t + kc * 64 * 128;
            for (int i = t; i < 8192; i += 256) sW1[i] = src[i];
        }
        __syncthreads();
        for (int k = 0; k < 64; k++) {
            float hv[4];
#pragma unroll
            for (int m = 0; m < 4; m++) hv[m] = sH[(qg + 16 * m) * 258 + kc * 64 + k];
            const float* wr = &sW1[k * 128 + og * 8];
            float4 wa = *(const float4*)wr;
            float4 wb = *(const float4*)(wr + 4);
#pragma unroll
            for (int m = 0; m < 4; m++) {
                acc2[m][0] += hv[m] * wa.x; acc2[m][1] += hv[m] * wa.y;
                acc2[m][2] += hv[m] * wa.z; acc2[m][3] += hv[m] * wa.w;
                acc2[m][4] += hv[m] * wb.x; acc2[m][5] += hv[m] * wb.y;
                acc2[m][6] += hv[m] * wb.z; acc2[m][7] += hv[m] * wb.w;
            }
        }
    }

    float bs[8];
#pragma unroll
    for (int n = 0; n < 8; n++) bs[n] = b1[og * 8 + n];

#pragma unroll
    for (int m = 0; m < 4; m++) {
        int qq = qbase + qg + 16 * m;
        float cy = coord[qq * 2 + 0];
        float cx = coord[qq * 2 + 1];
        float py = fminf(fmaxf(((cy + 1.0f) * 64.0f - 1.0f) * 0.5f, 0.0f), 63.0f);
        float px = fminf(fmaxf(((cx + 1.0f) * 64.0f - 1.0f) * 0.5f, 0.0f), 63.0f);
        float yf = floorf(py), xf = floorf(px);
        int y0 = (int)yf, x0 = (int)xf;
        float wy1 = py - yf, wx1 = px - xf;
        int y1 = min(y0 + 1, 63), x1 = min(x0 + 1, 63);
        float wts[4] = { (1.0f - wy1) * (1.0f - wx1), (1.0f - wy1) * wx1,
                         wy1 * (1.0f - wx1),          wy1 * wx1 };
        int ys[4] = { y0, y0, y1, y1 };
        int xs[4] = { x0, x1, x0, x1 };
        float sk[8] = { 0.f, 0.f, 0.f, 0.f, 0.f, 0.f, 0.f, 0.f };
#pragma unroll
        for (int tp = 0; tp < 4; tp++) {
            const float* fp = g_ft + ((b * HH + ys[tp]) * WW + xs[tp]) * CH + og * 8;
            float4 fa = *(const float4*)fp;
            float4 fb = *(const float4*)(fp + 4);
            float wgt = wts[tp];
            sk[0] += wgt * fa.x; sk[1] += wgt * fa.y; sk[2] += wgt * fa.z; sk[3] += wgt * fa.w;
            sk[4] += wgt * fb.x; sk[5] += wgt * fb.y; sk[6] += wgt * fb.z; sk[7] += wgt * fb.w;
        }
        float* op = out + qq * CH + og * 8;
        *(float4*)op = make_float4(acc2[m][0] + bs[0] + sk[0], acc2[m][1] + bs[1] + sk[1],
                                   acc2[m][2] + bs[2] + sk[2], acc2[m][3] + bs[3] + sk[3]);
        *(float4*)(op + 4) = make_float4(acc2[m][4] + bs[4] + sk[4], acc2[m][5] + bs[5] + sk[5],
                                         acc2[m][6] + bs[6] + sk[6], acc2[m][7] + bs[7] + sk[7]);
    }
}

// ---------------- launch ----------------
extern "C" void kernel_launch(void* const* d_in, const int* in_sizes, int n_in,
                              void* d_out, int out_size) {
    const float* x     = (const float*)d_in[0];
    const float* coord = (const float*)d_in[1];
    const float* cell  = (const float*)d_in[3];
    const float* qw    = (const float*)d_in[4];
    const float* qb    = (const float*)d_in[5];
    const float* kw    = (const float*)d_in[6];
    const float* kb    = (const float*)d_in[7];
    const float* vw    = (const float*)d_in[8];
    const float* vb    = (const float*)d_in[9];
    const float* pbw   = (const float*)d_in[10];
    const float* pbb   = (const float*)d_in[11];
    const float* w0    = (const float*)d_in[12];
    const float* b0    = (const float*)d_in[13];
    const float* w1    = (const float*)d_in[14];
    const float* b1    = (const float*)d_in[15];
    float* out = (float*)d_out;

    prep_w_kernel<<<(3 * 9 * CH * CH + 255) / 256, 256>>>(qw, kw, vw);
    prep_x_kernel<<<(BATCH * HH * WW * CH + 255) / 256, 256>>>(x);
    prep_small_kernel<<<(66048 + 255) / 256, 256>>>(w0, b0, w1, cell);
    conv_kernel<<<dim3(64, 2, 3), 256>>>(x, qb, kb, vb);
    attn_kernel<<<NQ / 8, 256>>>(coord, pbw, pbb);

    cudaFuncSetAttribute(mlp_kernel, cudaFuncAttributeMaxDynamicSharedMemorySize,
                         MLP_SMEM_FLOATS * 4);
    mlp_kernel<<<NQ / 64, 256, MLP_SMEM_FLOATS * 4>>>(coord, b1, out);
}

// round 2
// speedup vs baseline: 1.2285x; 1.2285x over previous
#include <cuda_runtime.h>
#include <cuda_bf16.h>
#include <math.h>

#define BATCH 2
#define CH    128
#define HH    64
#define WW    64
#define QPB   9216
#define NQ    18432
#define NHEAD 4
#define KWIN  7
#define KAREA 49

// ---------------- scratch (static device memory; no allocation) ----------------
__device__ float g_ft[BATCH*HH*WW*CH];       // feat NHWC (for skip)
__device__ float g_fq[BATCH*HH*WW*CH];       // conv q NHWC
__device__ float g_fk[BATCH*HH*WW*CH];       // conv k NHWC
__device__ float g_fv[BATCH*HH*WW*CH];       // conv v NHWC
__device__ unsigned g_xp[BATCH*HH*WW*CH];    // input NHWC packed (bf16hi<<16)|bf16lo
__device__ unsigned g_wp[3*9*CH*CH];         // weights [z][kk][co][ci] packed hi/lo
__device__ float g_w0t[128*256];             // w0 transposed [k][j] (first 128 inputs)
__device__ float g_w1t[256*128];             // w1 transposed [k][o]
__device__ float g_c0[2*256];                // per-batch effective bias for hidden
__device__ float g_agg[NQ*CH];               // attention output

static __device__ __forceinline__ unsigned pack_hl(float v) {
    __nv_bfloat16 hi = __float2bfloat16_rn(v);
    float hf = __bfloat162float(hi);
    __nv_bfloat16 lo = __float2bfloat16_rn(v - hf);
    return ((unsigned)__bfloat16_as_ushort(hi) << 16) | (unsigned)__bfloat16_as_ushort(lo);
}

// ---------------- prep kernels ----------------
__global__ void prep_w_kernel(const float* __restrict__ qw,
                              const float* __restrict__ kw,
                              const float* __restrict__ vw) {
    int idx = blockIdx.x * blockDim.x + threadIdx.x;
    if (idx >= 3 * 9 * CH * CH) return;
    int ci = idx & 127;
    int co = (idx >> 7) & 127;
    int kk = (idx >> 14) % 9;
    int z  = idx / (9 * CH * CH);
    const float* w = (z == 0) ? qw : ((z == 1) ? kw : vw);
    float v = w[(co * CH + ci) * 9 + kk];
    g_wp[idx] = pack_hl(v);
}

__global__ void prep_x_kernel(const float* __restrict__ x) {
    int idx = blockIdx.x * blockDim.x + threadIdx.x;
    if (idx >= BATCH * HH * WW * CH) return;
    int c = idx & 127;
    int p = (idx >> 7) & 4095;
    int b = idx >> 19;
    float v = x[(b * CH + c) * (HH * WW) + p];
    g_ft[idx] = v;
    g_xp[idx] = pack_hl(v);
}

__global__ void prep_small_kernel(const float* __restrict__ w0,
                                  const float* __restrict__ b0,
                                  const float* __restrict__ w1,
                                  const float* __restrict__ cell) {
    int idx = blockIdx.x * blockDim.x + threadIdx.x;
    if (idx < 32768) {
        int k = idx / 256, j = idx % 256;
        g_w0t[idx] = w0[j * 130 + k];
    } else if (idx < 65536) {
        int r = idx - 32768;
        int k = r / 128, o = r % 128;
        g_w1t[r] = w1[o * 256 + k];
    } else if (idx < 66048) {
        int r = idx - 65536;
        int b = r / 256, j = r % 256;
        float rc0 = cell[b * 2 + 0] * 64.0f;
        float rc1 = cell[b * 2 + 1] * 64.0f;
        g_c0[r] = b0[j] + w0[j * 130 + 128] * rc0 + w0[j * 130 + 129] * rc1;
    }
}

// ---------------- conv3x3 via mma.sync bf16 split-precision implicit GEMM ----------------
// block: 256 threads (8 warps, 2x4 m/n layout). tile: M=64 px (one image row) x N=128 co.
// K = 9 taps x 2 ci-chunks of 64. grid (64 rows, 2 batch, 3 conv).
// smem (dynamic, 55296 B):
//   sAh @0      : 64 x 72 bf16 (9216 B)
//   sAl @9216   : 64 x 72 bf16
//   sBh @18432  : 128 x 72 bf16 (18432 B)
//   sBl @36864  : 128 x 72 bf16
#define CONV_SMEM 55296

static __device__ __forceinline__ unsigned sptr(const void* p) {
    return (unsigned)__cvta_generic_to_shared(p);
}

#define LDMX4(r, addr) \
    asm volatile("ldmatrix.sync.aligned.m8n8.x4.shared.b16 {%0,%1,%2,%3}, [%4];" \
                 : "=r"((r)[0]), "=r"((r)[1]), "=r"((r)[2]), "=r"((r)[3]) : "r"(addr))

#define MMA16816(d, a, b0v, b1v) \
    asm volatile("mma.sync.aligned.m16n8k16.row.col.f32.bf16.bf16.f32 " \
                 "{%0,%1,%2,%3},{%4,%5,%6,%7},{%8,%9},{%0,%1,%2,%3};" \
                 : "+f"((d)[0]), "+f"((d)[1]), "+f"((d)[2]), "+f"((d)[3]) \
                 : "r"((a)[0]), "r"((a)[1]), "r"((a)[2]), "r"((a)[3]), "r"(b0v), "r"(b1v))

__global__ __launch_bounds__(256, 2) void convmma_kernel(const float* __restrict__ qb,
                                                         const float* __restrict__ kb,
                                                         const float* __restrict__ vb) {
    extern __shared__ char smc[];
    int t = threadIdx.x;
    int lane = t & 31;
    int w = t >> 5;
    int y0 = blockIdx.x;
    int b  = blockIdx.y;
    int z  = blockIdx.z;

    const float* bias = (z == 0) ? qb : ((z == 1) ? kb : vb);
    float* outp = (z == 0) ? g_fq : ((z == 1) ? g_fk : g_fv);

    int mw = w >> 2;        // 0..1  -> Mbase = mw*32
    int nw = w & 3;         // 0..3  -> Nbase = nw*32
    int Mbase = mw * 32;
    int Nbase = nw * 32;

    unsigned sb = sptr(smc);

    float acc[2][4][4];
#pragma unroll
    for (int mi = 0; mi < 2; mi++)
#pragma unroll
        for (int ni = 0; ni < 4; ni++)
#pragma unroll
            for (int r = 0; r < 4; r++) acc[mi][ni][r] = 0.0f;

    // precomputed ldmatrix address components
    int arow = (lane & 15);
    int acoloff = ((lane >> 4) << 3);
    int brow = ((lane >> 4) << 3) + (lane & 7);
    int bcoloff = ((lane >> 3) & 1) * 8;

    for (int kk = 0; kk < 9; kk++) {
        int dy = kk / 3 - 1;
        int dx = kk % 3 - 1;
        int gy = y0 + dy;
        const unsigned* wrow = g_wp + (z * 9 + kk) * CH * CH;
        for (int cic = 0; cic < 2; cic++) {
            __syncthreads();
            // --- fill A: 64 px x 64 ci ---
            for (int e = t; e < 2048; e += 256) {
                int px = e >> 5;
                int pair = e & 31;
                int gx = px + dx;
                uint2 p = make_uint2(0u, 0u);
                if ((unsigned)gy < 64u && (unsigned)gx < 64u)
                    p = *(const uint2*)&g_xp[((b * HH + gy) * WW + gx) * CH + cic * 64 + pair * 2];
                unsigned hi = __byte_perm(p.x, p.y, 0x7632);
                unsigned lo = __byte_perm(p.x, p.y, 0x5410);
                ((unsigned*)(smc + px * 144))[pair] = hi;
                ((unsigned*)(smc + 9216 + px * 144))[pair] = lo;
            }
            // --- fill B: 128 co x 64 ci ---
            for (int e = t; e < 4096; e += 256) {
                int co = e >> 5;
                int pair = e & 31;
                uint2 p = *(const uint2*)&wrow[co * CH + cic * 64 + pair * 2];
                unsigned hi = __byte_perm(p.x, p.y, 0x7632);
                unsigned lo = __byte_perm(p.x, p.y, 0x5410);
                ((unsigned*)(smc + 18432 + co * 144))[pair] = hi;
                ((unsigned*)(smc + 36864 + co * 144))[pair] = lo;
            }
            __syncthreads();

#pragma unroll
            for (int ksub = 0; ksub < 4; ksub++) {
                unsigned ah[2][4], al[2][4];
                int acol = acoloff + ksub * 16;
#pragma unroll
                for (int mi = 0; mi < 2; mi++) {
                    unsigned aaddr = sb + (unsigned)((Mbase + mi * 16 + arow) * 144 + acol * 2);
                    LDMX4(ah[mi], aaddr);
                    LDMX4(al[mi], aaddr + 9216u);
                }
#pragma unroll
                for (int nt = 0; nt < 2; nt++) {
                    int bcol = bcoloff + ksub * 16;
                    unsigned baddr = sb + 18432u +
                                     (unsigned)((Nbase + nt * 16 + brow) * 144 + bcol * 2);
                    unsigned bh[4], bl[4];
                    LDMX4(bh, baddr);
                    LDMX4(bl, baddr + 18432u);
#pragma unroll
                    for (int mi = 0; mi < 2; mi++) {
#pragma unroll
                        for (int h = 0; h < 2; h++) {
                            float* d = acc[mi][nt * 2 + h];
                            MMA16816(d, ah[mi], bh[2 * h], bh[2 * h + 1]);
                            MMA16816(d, ah[mi], bl[2 * h], bl[2 * h + 1]);
                            MMA16816(d, al[mi], bh[2 * h], bh[2 * h + 1]);
                        }
                    }
                }
            }
        }
    }

    // epilogue: acc -> NHWC float + bias
    int rr = lane >> 2;
    int c2 = (lane & 3) * 2;
#pragma unroll
    for (int mi = 0; mi < 2; mi++) {
#pragma unroll
        for (int ni = 0; ni < 4; ni++) {
            int co = Nbase + ni * 8 + c2;
            float b0v = bias[co], b1v = bias[co + 1];
            int px0 = Mbase + mi * 16 + rr;
            float* o0 = outp + ((b * HH + y0) * WW + px0) * CH + co;
            *(float2*)o0 = make_float2(acc[mi][ni][0] + b0v, acc[mi][ni][1] + b1v);
            float* o1 = outp + ((b * HH + y0) * WW + px0 + 8) * CH + co;
            *(float2*)o1 = make_float2(acc[mi][ni][2] + b0v, acc[mi][ni][3] + b1v);
        }
    }
}

// ---------------- attention: one warp per query ----------------
__global__ __launch_bounds__(256) void attn_kernel(const float* __restrict__ coord,
                                                   const float* __restrict__ pbw,
                                                   const float* __restrict__ pbb) {
    __shared__ float slog[8][NHEAD][KAREA];
    __shared__ float sbias[8][2][KWIN][NHEAD];
    __shared__ float spbw[NHEAD * 64];
    __shared__ float spbb[NHEAD];

    int t = threadIdx.x;
    int w = t >> 5;
    int lane = t & 31;
    if (t < NHEAD * 64) spbw[t] = pbw[t];
    if (t < NHEAD) spbb[t] = pbb[t];
    __syncthreads();

    int q = blockIdx.x * 8 + w;
    int b = q / QPB;
    float cy = coord[q * 2 + 0];
    float cx = coord[q * 2 + 1];
    float py = ((cy + 1.0f) * 64.0f - 1.0f) * 0.5f;
    float px = ((cx + 1.0f) * 64.0f - 1.0f) * 0.5f;
    float riy = rintf(py), rix = rintf(px);
    int iy0 = (int)riy, ix0 = (int)rix;
    float fy = py - riy, fx = px - rix;
    int h = lane >> 3;

    // bilinear q sample (zeros padding), 4 channels per lane (c = 4*lane..)
    float qv0 = 0.f, qv1 = 0.f, qv2 = 0.f, qv3 = 0.f;
    {
        float yf = floorf(py), xf = floorf(px);
        int y0 = (int)yf, x0 = (int)xf;
        float wy1 = py - yf, wx1 = px - xf;
#pragma unroll
        for (int dy2 = 0; dy2 < 2; dy2++)
#pragma unroll
            for (int dx2 = 0; dx2 < 2; dx2++) {
                int iy = y0 + dy2, ix = x0 + dx2;
                if ((unsigned)iy < 64u && (unsigned)ix < 64u) {
                    float wg = (dy2 ? wy1 : 1.0f - wy1) * (dx2 ? wx1 : 1.0f - wx1);
                    const float4 v = *(const float4*)(g_fq + (((b * HH + iy) * WW + ix) * CH + 4 * lane));
                    qv0 += wg * v.x; qv1 += wg * v.y; qv2 += wg * v.z; qv3 += wg * v.w;
                }
            }
    }

    // separable positional-bias tables: lanes 0..13 compute g_h(rel_y[d]) / e_h(rel_x[d])
    if (lane < 14) {
        int a = lane / 7;
        int dpos = lane - a * 7;
        float rel = 2.0f * ((a ? fx : fy) - (float)(dpos - 3));
        float a0 = 0.f, a1 = 0.f, a2 = 0.f, a3 = 0.f;
        const float step = 10.0f / 15.0f;
#pragma unroll
        for (int i = 0; i < 16; i++) {
            float fr = (i == 15) ? 1023.0f : (exp2f((float)i * step) - 1.0f);
            float s, c;
            sincosf(rel * fr, &s, &c);
            int si = a * 16 + i, ci2 = 32 + a * 16 + i;
            a0 += spbw[0 * 64 + si] * s + spbw[0 * 64 + ci2] * c;
            a1 += spbw[1 * 64 + si] * s + spbw[1 * 64 + ci2] * c;
            a2 += spbw[2 * 64 + si] * s + spbw[2 * 64 + ci2] * c;
            a3 += spbw[3 * 64 + si] * s + spbw[3 * 64 + ci2] * c;
        }
        if (a == 0) { a0 += spbb[0]; a1 += spbb[1]; a2 += spbb[2]; a3 += spbb[3]; }
        sbias[w][a][dpos][0] = a0; sbias[w][a][dpos][1] = a1;
        sbias[w][a][dpos][2] = a2; sbias[w][a][dpos][3] = a3;
    }
    __syncwarp();

    // pass 1: logits
    const float scale = 0.17677669529663687f;
    {
        int k = 0;
        for (int dy = -3; dy <= 3; dy++) {
            for (int dx = -3; dx <= 3; dx++, k++) {
                int iy = iy0 + dy, ix = ix0 + dx;
                float dot = 0.0f;
                if ((unsigned)iy < 64u && (unsigned)ix < 64u) {
                    const float4 kv = *(const float4*)(g_fk + (((b * HH + iy) * WW + ix) * CH + 4 * lane));
                    dot = qv0 * kv.x + qv1 * kv.y + qv2 * kv.z + qv3 * kv.w;
                }
                dot += __shfl_xor_sync(0xffffffffu, dot, 1);
                dot += __shfl_xor_sync(0xffffffffu, dot, 2);
                dot += __shfl_xor_sync(0xffffffffu, dot, 4);
                float lg = dot * scale + sbias[w][0][dy + 3][h] + sbias[w][1][dx + 3][h];
                if ((lane & 7) == 0) slog[w][h][k] = lg;
            }
        }
    }
    __syncwarp();

    float mx = -1e30f;
    for (int kk = 0; kk < KAREA; kk++) mx = fmaxf(mx, slog[w][h][kk]);
    float ssum = 0.0f;
    for (int kk = 0; kk < KAREA; kk++) ssum += expf(slog[w][h][kk] - mx);
    float inv = 1.0f / ssum;

    // pass 2: aggregate v
    float a0 = 0.f, a1 = 0.f, a2 = 0.f, a3 = 0.f;
    {
        int k = 0;
        for (int dy = -3; dy <= 3; dy++) {
            for (int dx = -3; dx <= 3; dx++, k++) {
                int iy = iy0 + dy, ix = ix0 + dx;
                if ((unsigned)iy < 64u && (unsigned)ix < 64u) {
                    float wg = expf(slog[w][h][k] - mx) * inv;
                    const float4 v = *(const float4*)(g_fv + (((b * HH + iy) * WW + ix) * CH + 4 * lane));
                    a0 += wg * v.x; a1 += wg * v.y; a2 += wg * v.z; a3 += wg * v.w;
                }
            }
        }
    }
    *(float4*)(g_agg + q * CH + 4 * lane) = make_float4(a0, a1, a2, a3);
}

// ---------------- MLP + skip ----------------
#define MLP_SMEM_FLOATS 24704
__global__ __launch_bounds__(256) void mlp_kernel(const float* __restrict__ coord,
                                                  const float* __restrict__ b1,
                                                  float* __restrict__ out) {
    extern __shared__ float sm[];
    float* sX = sm;
    float* sW = sm + 64 * 130;

    int t = threadIdx.x;
    int qbase = blockIdx.x * 64;
    int b = qbase / QPB;
    int qg = t & 15;
    int jg = t >> 4;

    for (int i = t; i < 64 * 128; i += 256) {
        int r = i >> 7, c2 = i & 127;
        sX[r * 130 + c2] = g_agg[(qbase + r) * CH + c2];
    }

    float acc1[4][16];
#pragma unroll
    for (int m = 0; m < 4; m++)
#pragma unroll
        for (int n = 0; n < 16; n++) acc1[m][n] = 0.0f;

    for (int kc = 0; kc < 4; kc++) {
        __syncthreads();
        {
            const float* src = g_w0t + kc * 32 * 256;
            for (int i = t; i < 8192; i += 256) sW[i] = src[i];
        }
        __syncthreads();
        for (int k = 0; k < 32; k++) {
            float xv[4];
#pragma unroll
            for (int m = 0; m < 4; m++) xv[m] = sX[(qg + 16 * m) * 130 + kc * 32 + k];
            const float* wr = &sW[k * 256 + jg * 16];
            float wrg[16];
#pragma unroll
            for (int n = 0; n < 16; n += 4) {
                float4 v = *(const float4*)(wr + n);
                wrg[n] = v.x; wrg[n + 1] = v.y; wrg[n + 2] = v.z; wrg[n + 3] = v.w;
            }
#pragma unroll
            for (int m = 0; m < 4; m++)
#pragma unroll
                for (int n = 0; n < 16; n++) acc1[m][n] += xv[m] * wrg[n];
        }
    }
    __syncthreads();

    float* sH = sm;
    float* sW1 = sm + 64 * 258;
#pragma unroll
    for (int m = 0; m < 4; m++) {
        int qq = qg + 16 * m;
#pragma unroll
        for (int jj = 0; jj < 16; jj++) {
            int j = jg * 16 + jj;
            float v = acc1[m][jj] + g_c0[b * 256 + j];
            float hgl = 0.5f * v * (1.0f + erff(v * 0.70710678118654752f));
            sH[qq * 258 + j] = hgl;
        }
    }

    int og = jg;
    float acc2[4][8];
#pragma unroll
    for (int m = 0; m < 4; m++)
#pragma unroll
        for (int n = 0; n < 8; n++) acc2[m][n] = 0.0f;

    for (int kc = 0; kc < 4; kc++) {
        __syncthreads();
        {
            const float* src = g_w1t + kc * 64 * 128;
            for (int i = t; i < 8192; i += 256) sW1[i] = src[i];
        }
        __syncthreads();
        for (int k = 0; k < 64; k++) {
            float hv[4];
#pragma unroll
            for (int m = 0; m < 4; m++) hv[m] = sH[(qg + 16 * m) * 258 + kc * 64 + k];
            const float* wr = &sW1[k * 128 + og * 8];
            float4 wa = *(const float4*)wr;
            float4 wb = *(const float4*)(wr + 4);
#pragma unroll
            for (int m = 0; m < 4; m++) {
                acc2[m][0] += hv[m] * wa.x; acc2[m][1] += hv[m] * wa.y;
                acc2[m][2] += hv[m] * wa.z; acc2[m][3] += hv[m] * wa.w;
                acc2[m][4] += hv[m] * wb.x; acc2[m][5] += hv[m] * wb.y;
                acc2[m][6] += hv[m] * wb.z; acc2[m][7] += hv[m] * wb.w;
            }
        }
    }

    float bs[8];
#pragma unroll
    for (int n = 0; n < 8; n++) bs[n] = b1[og * 8 + n];

#pragma unroll
    for (int m = 0; m < 4; m++) {
        int qq = qbase + qg + 16 * m;
        float cy = coord[qq * 2 + 0];
        float cx = coord[qq * 2 + 1];
        float py = fminf(fmaxf(((cy + 1.0f) * 64.0f - 1.0f) * 0.5f, 0.0f), 63.0f);
        float px = fminf(fmaxf(((cx + 1.0f) * 64.0f - 1.0f) * 0.5f, 0.0f), 63.0f);
        float yf = floorf(py), xf = floorf(px);
        int y0 = (int)yf, x0 = (int)xf;
        float wy1 = py - yf, wx1 = px - xf;
        int y1 = min(y0 + 1, 63), x1 = min(x0 + 1, 63);
        float wts[4] = { (1.0f - wy1) * (1.0f - wx1), (1.0f - wy1) * wx1,
                         wy1 * (1.0f - wx1),          wy1 * wx1 };
        int ys[4] = { y0, y0, y1, y1 };
        int xs[4] = { x0, x1, x0, x1 };
        float sk[8] = { 0.f, 0.f, 0.f, 0.f, 0.f, 0.f, 0.f, 0.f };
#pragma unroll
        for (int tp = 0; tp < 4; tp++) {
            const float* fp = g_ft + ((b * HH + ys[tp]) * WW + xs[tp]) * CH + og * 8;
            float4 fa = *(const float4*)fp;
            float4 fb = *(const float4*)(fp + 4);
            float wgt = wts[tp];
            sk[0] += wgt * fa.x; sk[1] += wgt * fa.y; sk[2] += wgt * fa.z; sk[3] += wgt * fa.w;
            sk[4] += wgt * fb.x; sk[5] += wgt * fb.y; sk[6] += wgt * fb.z; sk[7] += wgt * fb.w;
        }
        float* op = out + qq * CH + og * 8;
        *(float2*)op = make_float2(acc2[m][0] + bs[0] + sk[0], acc2[m][1] + bs[1] + sk[1]);
        *(float2*)(op + 2) = make_float2(acc2[m][2] + bs[2] + sk[2], acc2[m][3] + bs[3] + sk[3]);
        *(float2*)(op + 4) = make_float2(acc2[m][4] + bs[4] + sk[4], acc2[m][5] + bs[5] + sk[5]);
        *(float2*)(op + 6) = make_float2(acc2[m][6] + bs[6] + sk[6], acc2[m][7] + bs[7] + sk[7]);
    }
}

// ---------------- launch ----------------
extern "C" void kernel_launch(void* const* d_in, const int* in_sizes, int n_in,
                              void* d_out, int out_size) {
    const float* x     = (const float*)d_in[0];
    const float* coord = (const float*)d_in[1];
    const float* cell  = (const float*)d_in[3];
    const float* qw    = (const float*)d_in[4];
    const float* qb    = (const float*)d_in[5];
    const float* kw    = (const float*)d_in[6];
    const float* kb    = (const float*)d_in[7];
    const float* vw    = (const float*)d_in[8];
    const float* vb    = (const float*)d_in[9];
    const float* pbw   = (const float*)d_in[10];
    const float* pbb   = (const float*)d_in[11];
    const float* w0    = (const float*)d_in[12];
    const float* b0    = (const float*)d_in[13];
    const float* w1    = (const float*)d_in[14];
    const float* b1    = (const float*)d_in[15];
    float* out = (float*)d_out;

    prep_w_kernel<<<(3 * 9 * CH * CH + 255) / 256, 256>>>(qw, kw, vw);
    prep_x_kernel<<<(BATCH * HH * WW * CH + 255) / 256, 256>>>(x);
    prep_small_kernel<<<(66048 + 255) / 256, 256>>>(w0, b0, w1, cell);

    cudaFuncSetAttribute(convmma_kernel, cudaFuncAttributeMaxDynamicSharedMemorySize,
                         CONV_SMEM);
    convmma_kernel<<<dim3(64, 2, 3), 256, CONV_SMEM>>>(qb, kb, vb);

    attn_kernel<<<NQ / 8, 256>>>(coord, pbw, pbb);

    cudaFuncSetAttribute(mlp_kernel, cudaFuncAttributeMaxDynamicSharedMemorySize,
                         MLP_SMEM_FLOATS * 4);
    mlp_kernel<<<NQ / 64, 256, MLP_SMEM_FLOATS * 4>>>(coord, b1, out);
}

// round 3
// speedup vs baseline: 1.7177x; 1.3982x over previous
#include <cuda_runtime.h>
#include <cuda_bf16.h>
#include <math.h>

#define BATCH 2
#define CH    128
#define HH    64
#define WW    64
#define QPB   9216
#define NQ    18432
#define NHEAD 4
#define KWIN  7
#define KAREA 49

// ---------------- scratch (static device memory; no allocation) ----------------
__device__ float g_ft[BATCH*HH*WW*CH];          // feat NHWC (for skip)
__device__ float g_fq[BATCH*HH*WW*CH];          // conv q NHWC
__device__ float g_fk[BATCH*HH*WW*CH];          // conv k NHWC
__device__ float g_fv[BATCH*HH*WW*CH];          // conv v NHWC
__device__ __nv_bfloat16 g_xh[BATCH*HH*WW*CH];  // input NHWC bf16 hi
__device__ __nv_bfloat16 g_xl[BATCH*HH*WW*CH];  // input NHWC bf16 lo
__device__ __nv_bfloat16 g_wh[3*9*CH*CH];       // conv weights [z][kk][co][ci] hi
__device__ __nv_bfloat16 g_wl[3*9*CH*CH];       // lo
__device__ __nv_bfloat16 g_w0h[256*128];        // w0 [j][k] hi (k<128)
__device__ __nv_bfloat16 g_w0l[256*128];
__device__ __nv_bfloat16 g_w1h[128*256];        // w1 [o][k] hi
__device__ __nv_bfloat16 g_w1l[128*256];
__device__ float g_c0[2*256];                   // per-batch effective hidden bias
__device__ __nv_bfloat16 g_aggh[NQ*CH];         // attention output hi
__device__ __nv_bfloat16 g_aggl[NQ*CH];         // lo

static __device__ __forceinline__ void split_hl(float v, __nv_bfloat16& h, __nv_bfloat16& l) {
    h = __float2bfloat16_rn(v);
    l = __float2bfloat16_rn(v - __bfloat162float(h));
}

static __device__ __forceinline__ unsigned sptr(const void* p) {
    return (unsigned)__cvta_generic_to_shared(p);
}

#define CP_ASYNC16(dst, src, sz) \
    asm volatile("cp.async.cg.shared.global [%0], [%1], 16, %2;" :: "r"(dst), "l"(src), "r"(sz))
#define CP_COMMIT() asm volatile("cp.async.commit_group;")
#define CP_WAIT1()  asm volatile("cp.async.wait_group 1;")
#define CP_WAIT0()  asm volatile("cp.async.wait_group 0;")

#define LDMX4(r, addr) \
    asm volatile("ldmatrix.sync.aligned.m8n8.x4.shared.b16 {%0,%1,%2,%3}, [%4];" \
                 : "=r"((r)[0]), "=r"((r)[1]), "=r"((r)[2]), "=r"((r)[3]) : "r"(addr))

#define MMA16816(d, a, b0v, b1v) \
    asm volatile("mma.sync.aligned.m16n8k16.row.col.f32.bf16.bf16.f32 " \
                 "{%0,%1,%2,%3},{%4,%5,%6,%7},{%8,%9},{%0,%1,%2,%3};" \
                 : "+f"((d)[0]), "+f"((d)[1]), "+f"((d)[2]), "+f"((d)[3]) \
                 : "r"((a)[0]), "r"((a)[1]), "r"((a)[2]), "r"((a)[3]), "r"(b0v), "r"(b1v))

// ---------------- prep kernels ----------------
__global__ void prep_w_kernel(const float* __restrict__ qw,
                              const float* __restrict__ kw,
                              const float* __restrict__ vw) {
    int idx = blockIdx.x * blockDim.x + threadIdx.x;
    if (idx >= 3 * 9 * CH * CH) return;
    int ci = idx & 127;
    int co = (idx >> 7) & 127;
    int kk = (idx >> 14) % 9;
    int z  = idx / (9 * CH * CH);
    const float* w = (z == 0) ? qw : ((z == 1) ? kw : vw);
    float v = w[(co * CH + ci) * 9 + kk];
    split_hl(v, g_wh[idx], g_wl[idx]);
}

__global__ void prep_x_kernel(const float* __restrict__ x) {
    int idx = blockIdx.x * blockDim.x + threadIdx.x;
    if (idx >= BATCH * HH * WW * CH) return;
    int c = idx & 127;
    int p = (idx >> 7) & 4095;
    int b = idx >> 19;
    float v = x[(b * CH + c) * (HH * WW) + p];
    g_ft[idx] = v;
    split_hl(v, g_xh[idx], g_xl[idx]);
}

__global__ void prep_small_kernel(const float* __restrict__ w0,
                                  const float* __restrict__ b0,
                                  const float* __restrict__ w1,
                                  const float* __restrict__ cell) {
    int idx = blockIdx.x * blockDim.x + threadIdx.x;
    if (idx < 32768) {
        int j = idx >> 7, k = idx & 127;
        split_hl(w0[j * 130 + k], g_w0h[idx], g_w0l[idx]);
    } else if (idx < 65536) {
        int r = idx - 32768;
        split_hl(w1[r], g_w1h[r], g_w1l[r]);   // w1 is [o][256] row-major already
    } else if (idx < 66048) {
        int r = idx - 65536;
        int b = r / 256, j = r % 256;
        float rc0 = cell[b * 2 + 0] * 64.0f;
        float rc1 = cell[b * 2 + 1] * 64.0f;
        g_c0[r] = b0[j] + w0[j * 130 + 128] * rc0 + w0[j * 130 + 129] * rc1;
    }
}

// ---------------- conv3x3: cp.async double-buffered split-bf16 implicit GEMM ----------------
// block 256 thr (8 warps, 2m x 4n). tile M=64 px (one row) x N=128 co.
// 18 stages (9 taps x 2 ci-chunks of 64). stage buffer 55296 B:
//   Ah @0 (64x144B), Al @9216, Bh @18432 (128x144B), Bl @36864. double buffer = 110592 B.
#define CONV_STAGE 55296
#define CONV_SMEM  (2*CONV_STAGE)

__device__ __forceinline__ void conv_fill(int t, int s, unsigned bufb, int b, int y0, int z) {
    int kk = s >> 1, cic = s & 1;
    int dy = kk / 3 - 1, dx = kk - (kk / 3) * 3 - 1;
    int gy = y0 + dy;
    bool rowok = (unsigned)gy < 64u;
    int gyc = rowok ? gy : 0;
#pragma unroll
    for (int i = 0; i < 4; i++) {
        int e = t + i * 256;            // A tasks: 1024
        int half = e >> 9; int idx = e & 511; int px = idx >> 3; int seg = idx & 7;
        int gx = px + dx;
        bool ok = rowok && ((unsigned)gx < 64u);
        int gxc = ok ? gx : 0;
        const __nv_bfloat16* src = (half ? g_xl : g_xh) +
            (((b * 64 + gyc) * 64 + gxc) * 128 + cic * 64 + seg * 8);
        unsigned dst = bufb + (unsigned)(half * 9216 + px * 144 + seg * 16);
        CP_ASYNC16(dst, src, ok ? 16 : 0);
    }
    const __nv_bfloat16* wbh = g_wh + (z * 9 + kk) * 16384 + cic * 64;
    const __nv_bfloat16* wbl = g_wl + (z * 9 + kk) * 16384 + cic * 64;
#pragma unroll
    for (int i = 0; i < 8; i++) {
        int e = t + i * 256;            // B tasks: 2048
        int half = e >> 10; int idx = e & 1023; int co = idx >> 3; int seg = idx & 7;
        const __nv_bfloat16* src = (half ? wbl : wbh) + co * 128 + seg * 8;
        unsigned dst = bufb + (unsigned)(18432 + half * 18432 + co * 144 + seg * 16);
        CP_ASYNC16(dst, src, 16);
    }
}

__global__ __launch_bounds__(256, 1) void convmma_kernel(const float* __restrict__ qb,
                                                         const float* __restrict__ kb,
                                                         const float* __restrict__ vb) {
    extern __shared__ char smc[];
    int t = threadIdx.x;
    int lane = t & 31;
    int w = t >> 5;
    int y0 = blockIdx.x;
    int b  = blockIdx.y;
    int z  = blockIdx.z;

    const float* bias = (z == 0) ? qb : ((z == 1) ? kb : vb);
    float* outp = (z == 0) ? g_fq : ((z == 1) ? g_fk : g_fv);

    int Mbase = (w >> 2) * 32;
    int Nbase = (w & 3) * 32;
    unsigned sb = sptr(smc);

    float acc[2][4][4];
#pragma unroll
    for (int mi = 0; mi < 2; mi++)
#pragma unroll
        for (int ni = 0; ni < 4; ni++)
#pragma unroll
            for (int r = 0; r < 4; r++) acc[mi][ni][r] = 0.0f;

    int arow = (lane & 15);
    int acoloff = ((lane >> 4) << 3);
    int brow = ((lane >> 4) << 3) + (lane & 7);
    int bcoloff = ((lane >> 3) & 1) * 8;

    conv_fill(t, 0, sb, b, y0, z);
    CP_COMMIT();

    for (int s = 0; s < 18; s++) {
        if (s < 17) {
            conv_fill(t, s + 1, sb + ((unsigned)((s + 1) & 1)) * CONV_STAGE, b, y0, z);
            CP_COMMIT();
            CP_WAIT1();
        } else {
            CP_WAIT0();
        }
        __syncthreads();
        unsigned bufb = sb + ((unsigned)(s & 1)) * CONV_STAGE;
#pragma unroll
        for (int ksub = 0; ksub < 4; ksub++) {
            unsigned ah[2][4], al[2][4];
            int acol = acoloff + ksub * 16;
#pragma unroll
            for (int mi = 0; mi < 2; mi++) {
                unsigned aaddr = bufb + (unsigned)((Mbase + mi * 16 + arow) * 144 + acol * 2);
                LDMX4(ah[mi], aaddr);
                LDMX4(al[mi], aaddr + 9216u);
            }
#pragma unroll
            for (int nt = 0; nt < 2; nt++) {
                int bcol = bcoloff + ksub * 16;
                unsigned baddr = bufb + 18432u +
                                 (unsigned)((Nbase + nt * 16 + brow) * 144 + bcol * 2);
                unsigned bh[4], bl[4];
                LDMX4(bh, baddr);
                LDMX4(bl, baddr + 18432u);
#pragma unroll
                for (int mi = 0; mi < 2; mi++) {
#pragma unroll
                    for (int h = 0; h < 2; h++) {
                        float* d = acc[mi][nt * 2 + h];
                        MMA16816(d, ah[mi], bh[2 * h], bh[2 * h + 1]);
                        MMA16816(d, ah[mi], bl[2 * h], bl[2 * h + 1]);
                        MMA16816(d, al[mi], bh[2 * h], bh[2 * h + 1]);
                    }
                }
            }
        }
        __syncthreads();
    }

    int rr = lane >> 2;
    int c2 = (lane & 3) * 2;
#pragma unroll
    for (int mi = 0; mi < 2; mi++) {
#pragma unroll
        for (int ni = 0; ni < 4; ni++) {
            int co = Nbase + ni * 8 + c2;
            float b0v = bias[co], b1v = bias[co + 1];
            int px0 = Mbase + mi * 16 + rr;
            float* o0 = outp + ((b * HH + y0) * WW + px0) * CH + co;
            *(float2*)o0 = make_float2(acc[mi][ni][0] + b0v, acc[mi][ni][1] + b1v);
            float* o1 = outp + ((b * HH + y0) * WW + px0 + 8) * CH + co;
            *(float2*)o1 = make_float2(acc[mi][ni][2] + b0v, acc[mi][ni][3] + b1v);
        }
    }
}

// ---------------- attention: one warp per query ----------------
__global__ __launch_bounds__(256) void attn_kernel(const float* __restrict__ coord,
                                                   const float* __restrict__ pbw,
                                                   const float* __restrict__ pbb) {
    __shared__ float slog[8][NHEAD][KAREA];
    __shared__ float sbias[8][2][KWIN][NHEAD];
    __shared__ float spbw[NHEAD * 64];
    __shared__ float spbb[NHEAD];

    int t = threadIdx.x;
    int w = t >> 5;
    int lane = t & 31;
    if (t < NHEAD * 64) spbw[t] = pbw[t];
    if (t < NHEAD) spbb[t] = pbb[t];
    __syncthreads();

    int q = blockIdx.x * 8 + w;
    int b = q / QPB;
    float cy = coord[q * 2 + 0];
    float cx = coord[q * 2 + 1];
    float py = ((cy + 1.0f) * 64.0f - 1.0f) * 0.5f;
    float px = ((cx + 1.0f) * 64.0f - 1.0f) * 0.5f;
    float riy = rintf(py), rix = rintf(px);
    int iy0 = (int)riy, ix0 = (int)rix;
    float fy = py - riy, fx = px - rix;
    int h = lane >> 3;

    float qv0 = 0.f, qv1 = 0.f, qv2 = 0.f, qv3 = 0.f;
    {
        float yf = floorf(py), xf = floorf(px);
        int y0 = (int)yf, x0 = (int)xf;
        float wy1 = py - yf, wx1 = px - xf;
#pragma unroll
        for (int dy2 = 0; dy2 < 2; dy2++)
#pragma unroll
            for (int dx2 = 0; dx2 < 2; dx2++) {
                int iy = y0 + dy2, ix = x0 + dx2;
                if ((unsigned)iy < 64u && (unsigned)ix < 64u) {
                    float wg = (dy2 ? wy1 : 1.0f - wy1) * (dx2 ? wx1 : 1.0f - wx1);
                    const float4 v = *(const float4*)(g_fq + (((b * HH + iy) * WW + ix) * CH + 4 * lane));
                    qv0 += wg * v.x; qv1 += wg * v.y; qv2 += wg * v.z; qv3 += wg * v.w;
                }
            }
    }

    if (lane < 14) {
        int a = lane / 7;
        int dpos = lane - a * 7;
        float rel = 2.0f * ((a ? fx : fy) - (float)(dpos - 3));
        float a0 = 0.f, a1 = 0.f, a2 = 0.f, a3 = 0.f;
        const float step = 10.0f / 15.0f;
#pragma unroll
        for (int i = 0; i < 16; i++) {
            float fr = (i == 15) ? 1023.0f : (exp2f((float)i * step) - 1.0f);
            float s, c;
            sincosf(rel * fr, &s, &c);
            int si = a * 16 + i, ci2 = 32 + a * 16 + i;
            a0 += spbw[0 * 64 + si] * s + spbw[0 * 64 + ci2] * c;
            a1 += spbw[1 * 64 + si] * s + spbw[1 * 64 + ci2] * c;
            a2 += spbw[2 * 64 + si] * s + spbw[2 * 64 + ci2] * c;
            a3 += spbw[3 * 64 + si] * s + spbw[3 * 64 + ci2] * c;
        }
        if (a == 0) { a0 += spbb[0]; a1 += spbb[1]; a2 += spbb[2]; a3 += spbb[3]; }
        sbias[w][a][dpos][0] = a0; sbias[w][a][dpos][1] = a1;
        sbias[w][a][dpos][2] = a2; sbias[w][a][dpos][3] = a3;
    }
    __syncwarp();

    const float scale = 0.17677669529663687f;
    {
        int k = 0;
        for (int dy = -3; dy <= 3; dy++) {
            for (int dx = -3; dx <= 3; dx++, k++) {
                int iy = iy0 + dy, ix = ix0 + dx;
                float dot = 0.0f;
                if ((unsigned)iy < 64u && (unsigned)ix < 64u) {
                    const float4 kv = *(const float4*)(g_fk + (((b * HH + iy) * WW + ix) * CH + 4 * lane));
                    dot = qv0 * kv.x + qv1 * kv.y + qv2 * kv.z + qv3 * kv.w;
                }
                dot += __shfl_xor_sync(0xffffffffu, dot, 1);
                dot += __shfl_xor_sync(0xffffffffu, dot, 2);
                dot += __shfl_xor_sync(0xffffffffu, dot, 4);
                float lg = dot * scale + sbias[w][0][dy + 3][h] + sbias[w][1][dx + 3][h];
                if ((lane & 7) == 0) slog[w][h][k] = lg;
            }
        }
    }
    __syncwarp();

    float mx = -1e30f;
    for (int kk = 0; kk < KAREA; kk++) mx = fmaxf(mx, slog[w][h][kk]);
    float ssum = 0.0f;
    for (int kk = 0; kk < KAREA; kk++) ssum += expf(slog[w][h][kk] - mx);
    float inv = 1.0f / ssum;

    float a0 = 0.f, a1 = 0.f, a2 = 0.f, a3 = 0.f;
    {
        int k = 0;
        for (int dy = -3; dy <= 3; dy++) {
            for (int dx = -3; dx <= 3; dx++, k++) {
                int iy = iy0 + dy, ix = ix0 + dx;
                if ((unsigned)iy < 64u && (unsigned)ix < 64u) {
                    float wg = expf(slog[w][h][k] - mx) * inv;
                    const float4 v = *(const float4*)(g_fv + (((b * HH + iy) * WW + ix) * CH + 4 * lane));
                    a0 += wg * v.x; a1 += wg * v.y; a2 += wg * v.z; a3 += wg * v.w;
                }
            }
        }
    }
    // store split hi/lo bf16 for MLP tensor-core consumption
    int base = q * CH + 4 * lane;
    __nv_bfloat16 h0, l0, h1, l1, h2, l2, h3, l3;
    split_hl(a0, h0, l0); split_hl(a1, h1, l1);
    split_hl(a2, h2, l2); split_hl(a3, h3, l3);
    __nv_bfloat162 p;
    p.x = h0; p.y = h1; *(__nv_bfloat162*)(g_aggh + base) = p;
    p.x = h2; p.y = h3; *(__nv_bfloat162*)(g_aggh + base + 2) = p;
    p.x = l0; p.y = l1; *(__nv_bfloat162*)(g_aggl + base) = p;
    p.x = l2; p.y = l3; *(__nv_bfloat162*)(g_aggl + base + 2) = p;
}

// ---------------- MLP via split-bf16 mma + skip ----------------
// block: 64 q, 256 thr (8 warps: 2m x 4n). smem layout (bytes):
//   GEMM1: sXh @0 (64x272), sXl @17408; W0 stage @34816: hi (256x144=36864), lo @71680. end 108544.
//   GEMM2: sHh @0 (64x528=33792), sHl @33792; W1 stage @67584: hi (128x144=18432), lo @86016. end 104448.
#define MLP_SMEM 108544
__global__ __launch_bounds__(256, 1) void mlpmma_kernel(const float* __restrict__ coord,
                                                        const float* __restrict__ b1,
                                                        float* __restrict__ out) {
    extern __shared__ char sm8[];
    unsigned sb = sptr(sm8);
    int t = threadIdx.x, lane = t & 31, w = t >> 5;
    int mw = w >> 2, nw2 = w & 3;
    int qbase = blockIdx.x * 64;
    int b = qbase / QPB;

    int arow = (lane & 15);
    int acoloff = ((lane >> 4) << 3);
    int brow = ((lane >> 4) << 3) + (lane & 7);
    int bcoloff = ((lane >> 3) & 1) * 8;

    // fill X (agg hi/lo): 64 rows x 256B each half
#pragma unroll
    for (int i = 0; i < 8; i++) {
        int e = t + i * 256;
        int half = e >> 10; int idx = e & 1023; int r = idx >> 4; int seg = idx & 15;
        const uint4* src = (const uint4*)((half ? g_aggl : g_aggh) + (qbase + r) * 128) + seg;
        *(uint4*)(sm8 + half * 17408 + r * 272 + seg * 16) = *src;
    }

    float acc1[2][8][4];
#pragma unroll
    for (int mi = 0; mi < 2; mi++)
#pragma unroll
        for (int n = 0; n < 8; n++)
#pragma unroll
            for (int r = 0; r < 4; r++) acc1[mi][n][r] = 0.0f;

    for (int kc = 0; kc < 2; kc++) {
        __syncthreads();
#pragma unroll
        for (int i = 0; i < 16; i++) {      // W0 chunk: 256 j x 128B per half
            int e = t + i * 256;
            int half = e >> 11; int idx = e & 2047; int j = idx >> 3; int seg = idx & 7;
            const uint4* src = (const uint4*)((half ? g_w0l : g_w0h) + j * 128 + kc * 64) + seg;
            *(uint4*)(sm8 + 34816 + half * 36864 + j * 144 + seg * 16) = *src;
        }
        __syncthreads();
#pragma unroll
        for (int ksub = 0; ksub < 4; ksub++) {
            unsigned ah[2][4], al[2][4];
            int acolb = (kc * 64 + ksub * 16 + acoloff) * 2;
#pragma unroll
            for (int mi = 0; mi < 2; mi++) {
                unsigned aaddr = sb + (unsigned)((mw * 32 + mi * 16 + arow) * 272 + acolb);
                LDMX4(ah[mi], aaddr);
                LDMX4(al[mi], aaddr + 17408u);
            }
#pragma unroll
            for (int nt = 0; nt < 4; nt++) {
                unsigned baddr = sb + 34816u +
                    (unsigned)((nw2 * 64 + nt * 16 + brow) * 144 + (bcoloff + ksub * 16) * 2);
                unsigned bh[4], bl[4];
                LDMX4(bh, baddr);
                LDMX4(bl, baddr + 36864u);
#pragma unroll
                for (int mi = 0; mi < 2; mi++)
#pragma unroll
                    for (int h = 0; h < 2; h++) {
                        float* d = acc1[mi][nt * 2 + h];
                        MMA16816(d, ah[mi], bh[2 * h], bh[2 * h + 1]);
                        MMA16816(d, ah[mi], bl[2 * h], bl[2 * h + 1]);
                        MMA16816(d, al[mi], bh[2 * h], bh[2 * h + 1]);
                    }
            }
        }
    }
    __syncthreads();

    // bias + gelu + split into H hi/lo in smem
    {
        int r0 = mw * 32 + (lane >> 2);
        int cb = nw2 * 64 + (lane & 3) * 2;
#pragma unroll
        for (int mi = 0; mi < 2; mi++) {
#pragma unroll
            for (int n = 0; n < 8; n++) {
                int c = cb + n * 8;
                float c0a = g_c0[b * 256 + c];
                float c0b = g_c0[b * 256 + c + 1];
#pragma unroll
                for (int rs = 0; rs < 2; rs++) {
                    float v0 = acc1[mi][n][rs * 2 + 0] + c0a;
                    float v1 = acc1[mi][n][rs * 2 + 1] + c0b;
                    float gl0 = 0.5f * v0 * (1.0f + erff(v0 * 0.70710678118654752f));
                    float gl1 = 0.5f * v1 * (1.0f + erff(v1 * 0.70710678118654752f));
                    __nv_bfloat16 h0, l0, h1, l1;
                    split_hl(gl0, h0, l0); split_hl(gl1, h1, l1);
                    int row = r0 + mi * 16 + rs * 8;
                    __nv_bfloat162 hp; hp.x = h0; hp.y = h1;
                    __nv_bfloat162 lp; lp.x = l0; lp.y = l1;
                    *(__nv_bfloat162*)(sm8 + row * 528 + c * 2) = hp;
                    *(__nv_bfloat162*)(sm8 + 33792 + row * 528 + c * 2) = lp;
                }
            }
        }
    }

    float acc2[2][4][4];
#pragma unroll
    for (int mi = 0; mi < 2; mi++)
#pragma unroll
        for (int n = 0; n < 4; n++)
#pragma unroll
            for (int r = 0; r < 4; r++) acc2[mi][n][r] = 0.0f;

    for (int kc = 0; kc < 4; kc++) {
        __syncthreads();
#pragma unroll
        for (int i = 0; i < 8; i++) {      // W1 chunk: 128 o x 128B per half
            int e = t + i * 256;
            int half = e >> 10; int idx = e & 1023; int o = idx >> 3; int seg = idx & 7;
            const uint4* src = (const uint4*)((half ? g_w1l : g_w1h) + o * 256 + kc * 64) + seg;
            *(uint4*)(sm8 + 67584 + half * 18432 + o * 144 + seg * 16) = *src;
        }
        __syncthreads();
#pragma unroll
        for (int ksub = 0; ksub < 4; ksub++) {
            unsigned ah[2][4], al[2][4];
            int acolb = (kc * 64 + ksub * 16 + acoloff) * 2;
#pragma unroll
            for (int mi = 0; mi < 2; mi++) {
                unsigned aaddr = sb + (unsigned)((mw * 32 + mi * 16 + arow) * 528 + acolb);
                LDMX4(ah[mi], aaddr);
                LDMX4(al[mi], aaddr + 33792u);
            }
#pragma unroll
            for (int nt = 0; nt < 2; nt++) {
                unsigned baddr = sb + 67584u +
                    (unsigned)((nw2 * 32 + nt * 16 + brow) * 144 + (bcoloff + ksub * 16) * 2);
                unsigned bh[4], bl[4];
                LDMX4(bh, baddr);
                LDMX4(bl, baddr + 18432u);
#pragma unroll
                for (int mi = 0; mi < 2; mi++)
#pragma unroll
                    for (int h = 0; h < 2; h++) {
                        float* d = acc2[mi][nt * 2 + h];
                        MMA16816(d, ah[mi], bh[2 * h], bh[2 * h + 1]);
                        MMA16816(d, ah[mi], bl[2 * h], bl[2 * h + 1]);
                        MMA16816(d, al[mi], bh[2 * h], bh[2 * h + 1]);
                    }
            }
        }
    }

    // epilogue: bias + bilinear-border skip + store
#pragma unroll
    for (int mi = 0; mi < 2; mi++) {
#pragma unroll
        for (int rs = 0; rs < 2; rs++) {
            int q = qbase + mw * 32 + mi * 16 + (lane >> 2) + rs * 8;
            float cy = coord[q * 2 + 0];
            float cx = coord[q * 2 + 1];
            float py = fminf(fmaxf(((cy + 1.0f) * 64.0f - 1.0f) * 0.5f, 0.0f), 63.0f);
            float px = fminf(fmaxf(((cx + 1.0f) * 64.0f - 1.0f) * 0.5f, 0.0f), 63.0f);
            float yf = floorf(py), xf = floorf(px);
            int y0 = (int)yf, x0 = (int)xf;
            float wy1 = py - yf, wx1 = px - xf;
            int y1 = min(y0 + 1, 63), x1 = min(x0 + 1, 63);
            float wts[4] = { (1.0f - wy1) * (1.0f - wx1), (1.0f - wy1) * wx1,
                             wy1 * (1.0f - wx1),          wy1 * wx1 };
            const float* fp0 = g_ft + ((b * HH + y0) * WW + x0) * CH;
            const float* fp1 = g_ft + ((b * HH + y0) * WW + x1) * CH;
            const float* fp2 = g_ft + ((b * HH + y1) * WW + x0) * CH;
            const float* fp3 = g_ft + ((b * HH + y1) * WW + x1) * CH;
#pragma unroll
            for (int n = 0; n < 4; n++) {
                int c = nw2 * 32 + n * 8 + (lane & 3) * 2;
                float2 f0 = *(const float2*)(fp0 + c);
                float2 f1 = *(const float2*)(fp1 + c);
                float2 f2 = *(const float2*)(fp2 + c);
                float2 f3 = *(const float2*)(fp3 + c);
                float s0 = wts[0] * f0.x + wts[1] * f1.x + wts[2] * f2.x + wts[3] * f3.x;
                float s1 = wts[0] * f0.y + wts[1] * f1.y + wts[2] * f2.y + wts[3] * f3.y;
                float2 o;
                o.x = acc2[mi][n][rs * 2 + 0] + b1[c] + s0;
                o.y = acc2[mi][n][rs * 2 + 1] + b1[c + 1] + s1;
                *(float2*)(out + q * CH + c) = o;
            }
        }
    }
}

// ---------------- launch ----------------
extern "C" void kernel_launch(void* const* d_in, const int* in_sizes, int n_in,
                              void* d_out, int out_size) {
    const float* x     = (const float*)d_in[0];
    const float* coord = (const float*)d_in[1];
    const float* cell  = (const float*)d_in[3];
    const float* qw    = (const float*)d_in[4];
    const float* qb    = (const float*)d_in[5];
    const float* kw    = (const float*)d_in[6];
    const float* kb    = (const float*)d_in[7];
    const float* vw    = (const float*)d_in[8];
    const float* vb    = (const float*)d_in[9];
    const float* pbw   = (const float*)d_in[10];
    const float* pbb   = (const float*)d_in[11];
    const float* w0    = (const float*)d_in[12];
    const float* b0    = (const float*)d_in[13];
    const float* w1    = (const float*)d_in[14];
    const float* b1    = (const float*)d_in[15];
    float* out = (float*)d_out;

    prep_w_kernel<<<(3 * 9 * CH * CH + 255) / 256, 256>>>(qw, kw, vw);
    prep_x_kernel<<<(BATCH * HH * WW * CH + 255) / 256, 256>>>(x);
    prep_small_kernel<<<(66048 + 255) / 256, 256>>>(w0, b0, w1, cell);

    cudaFuncSetAttribute(convmma_kernel, cudaFuncAttributeMaxDynamicSharedMemorySize, CONV_SMEM);
    convmma_kernel<<<dim3(64, 2, 3), 256, CONV_SMEM>>>(qb, kb, vb);

    attn_kernel<<<NQ / 8, 256>>>(coord, pbw, pbb);

    cudaFuncSetAttribute(mlpmma_kernel, cudaFuncAttributeMaxDynamicSharedMemorySize, MLP_SMEM);
    mlpmma_kernel<<<NQ / 64, 256, MLP_SMEM>>>(coord, b1, out);
}